// round 14
// baseline (speedup 1.0000x reference)
#include <cuda_runtime.h>

// Problem constants (fixed by the reference):
//   x: [B, 96, 128, 128] fp32, depthwise 3x3, stride 1, pad 1
#define C_DIM 96
#define HW 128
#define PLANE (HW * HW)          // 16384
#define CR 24                    // C_DIM / 4
#define WDYN_PER_B (C_DIM * 9)   // 864
#define BN_EPS 1e-5f
#define MAX_B 64

// Scratch (allocation-free rule: __device__ globals)
__device__ float g_pooled[MAX_B * C_DIM];
__device__ float g_wdyn[MAX_B * WDYN_PER_B];
__device__ int   g_sync[2 * MAX_B];   // [0..MAX_B): counters, [MAX_B..): flags

// ---------------------------------------------------------------------------
// Fully fused kernel: pool -> (last finisher per sample) weights -> conv,
// one block per (b,c) plane. Conv phase re-reads the exact bytes this block
// just pooled -> L2-hot. Per-sample release via acquire/release flag; the
// cp.async tile fills are issued BEFORE the flag wait (they don't need the
// weights), so the wait hides under load latency.
// ---------------------------------------------------------------------------
#define ROWS 16
#define TROWS (ROWS + 2)   // 18
#define TW 132             // 128 data cols + pad (row stride 528B, 16B-aligned)
#define NTILES (HW / ROWS) // 8

__device__ __forceinline__ void cp16(float* dst, const float* src) {
    unsigned d = (unsigned)__cvta_generic_to_shared(dst);
    asm volatile("cp.async.cg.shared.global [%0], [%1], 16;" :: "r"(d), "l"(src) : "memory");
}
#define CP_COMMIT() asm volatile("cp.async.commit_group;" ::: "memory")
#define CP_WAIT1()  asm volatile("cp.async.wait_group 1;" ::: "memory")
#define CP_WAIT0()  asm volatile("cp.async.wait_group 0;" ::: "memory")

__global__ __launch_bounds__(256) void fused_kernel(
    const float* __restrict__ x,
    const float* __restrict__ w1,      // [CR, C_DIM]
    const float* __restrict__ gamma,
    const float* __restrict__ beta,
    const float* __restrict__ rmean,
    const float* __restrict__ rvar,
    const float* __restrict__ w2,      // [WDYN_PER_B, CR]
    const float* __restrict__ b2,
    const float* __restrict__ bias,
    float* __restrict__ out,
    float* __restrict__ pooled,
    float* __restrict__ wdyn,
    int* __restrict__ sync) {
    const int plane = blockIdx.x;
    const int b  = plane / C_DIM;
    const int ch = plane % C_DIM;
    const int tid = threadIdx.y * 32 + threadIdx.x;
    const int lane = threadIdx.x;

    int* cnt  = sync;
    int* flag = sync + MAX_B;

    __shared__ float tile[3][TROWS][TW];
    __shared__ float ws[8];
    __shared__ float p[C_DIM];
    __shared__ float h1[CR];
    __shared__ int last;

    const float* xp = x + (size_t)plane * PLANE;
    float* op = out + (size_t)plane * PLANE;

    // ================= phase 1: pool this plane =================
    {
        const float4* xq = reinterpret_cast<const float4*>(xp);
        float s = 0.f;
#pragma unroll 4
        for (int i = tid; i < PLANE / 4; i += 256) {
            float4 v = xq[i];
            s += (v.x + v.y) + (v.z + v.w);
        }
#pragma unroll
        for (int o = 16; o > 0; o >>= 1) s += __shfl_xor_sync(0xffffffffu, s, o);
        if ((tid & 31) == 0) ws[tid >> 5] = s;
        __syncthreads();
        if (tid < 8) {
            float t = ws[tid];
#pragma unroll
            for (int o = 4; o > 0; o >>= 1) t += __shfl_xor_sync(0xffu, t, o);
            if (tid == 0) {
                pooled[plane] = t * (1.f / (float)PLANE);
                __threadfence();                     // publish before counting
                const int old = atomicAdd(&cnt[b], 1);
                last = (old == C_DIM - 1) ? 1 : 0;
            }
        }
        __syncthreads();
    }

    // ============ phase 2 (last finisher only): sample-b weights ============
    if (last) {
        if (tid < C_DIM) p[tid] = __ldcg(&pooled[b * C_DIM + tid]);
        __syncthreads();
        if (tid < CR) {
            float t = 0.f;
            const float* wr = w1 + tid * C_DIM;
#pragma unroll 8
            for (int c = 0; c < C_DIM; c++) t += p[c] * wr[c];
            t = (t - rmean[tid]) * rsqrtf(rvar[tid] + BN_EPS) * gamma[tid] + beta[tid];
            h1[tid] = 1.f / (1.f + __expf(-t));
        }
        __syncthreads();
        for (int o = tid; o < WDYN_PER_B; o += 256) {
            float t = b2[o];
            const float* wr = w2 + o * CR;
#pragma unroll
            for (int j = 0; j < CR; j++) t += h1[j] * wr[j];
            wdyn[b * WDYN_PER_B + o] = t;
        }
        __threadfence();
        __syncthreads();
        if (tid == 0) atomicExch(&flag[b], 1);       // release sample b
    }

    // ================= phase 3: conv (L2-hot re-read) =================
    auto fill = [&](int buf, int row0) {
#pragma unroll
        for (int k = 0; k < 2; k++) {
            const int i = tid + k * 256;          // 0..511
            const int r = i >> 5, cq = i & 31;
            const int gr = row0 - 1 + r;
            float* dst = &tile[buf][r][cq * 4];
            if ((unsigned)gr < (unsigned)HW)
                cp16(dst, xp + gr * HW + cq * 4);
            else
                *reinterpret_cast<float4*>(dst) = make_float4(0.f, 0.f, 0.f, 0.f);
        }
        if (tid < TROWS * 32 - 512) {             // rows 16,17
            const int i = tid + 512;
            const int r = i >> 5, cq = i & 31;
            const int gr = row0 - 1 + r;
            float* dst = &tile[buf][r][cq * 4];
            if ((unsigned)gr < (unsigned)HW)
                cp16(dst, xp + gr * HW + cq * 4);
            else
                *reinterpret_cast<float4*>(dst) = make_float4(0.f, 0.f, 0.f, 0.f);
        }
    };

    // issue the first two tile fills BEFORE waiting on the flag
    fill(0, 0);
    CP_COMMIT();
    fill(1, ROWS);
    CP_COMMIT();

    // acquire-poll sample-b flag (tid 0 only; wait hides under cp.asyncs)
    if (tid == 0) {
        int f;
        do {
            asm volatile("ld.global.acquire.gpu.b32 %0, [%1];"
                         : "=r"(f) : "l"(&flag[b]) : "memory");
            if (!f) __nanosleep(64);
        } while (!f);
    }
    __syncthreads();

    // per-channel dynamic 3x3 weights (L2 reads — written by another SM)
    float w[9];
    const float* wp = wdyn + (size_t)plane * 9;
#pragma unroll
    for (int i = 0; i < 9; i++) w[i] = __ldcg(wp + i);
    const float bv = __ldg(bias + ch);

    const int cx = threadIdx.x * 4;

    auto compute = [&](int buf, int row0) {
#pragma unroll
        for (int j = 0; j < 2; j++) {
            const int rt = threadIdx.y * 2 + j;
            float a0 = bv, a1 = bv, a2 = bv, a3 = bv;
#pragma unroll
            for (int dy = 0; dy < 3; dy++) {
                const float4 v = *reinterpret_cast<const float4*>(&tile[buf][rt + dy][cx]);
                float vl = __shfl_up_sync(0xffffffffu, v.w, 1);
                float vr = __shfl_down_sync(0xffffffffu, v.x, 1);
                if (lane == 0)  vl = 0.f;
                if (lane == 31) vr = 0.f;
                const float w0 = w[dy * 3 + 0], w1_ = w[dy * 3 + 1], w2_ = w[dy * 3 + 2];
                a0 += vl  * w0 + v.x * w1_ + v.y * w2_;
                a1 += v.x * w0 + v.y * w1_ + v.z * w2_;
                a2 += v.y * w0 + v.z * w1_ + v.w * w2_;
                a3 += v.z * w0 + v.w * w1_ + vr  * w2_;
            }
            float4 o; o.x = a0; o.y = a1; o.z = a2; o.w = a3;
            __stcs(reinterpret_cast<float4*>(op + (row0 + rt) * HW + cx), o);
        }
    };

    int buf = 0;
#pragma unroll
    for (int t = 0; t < NTILES; t++) {
        if (t < NTILES - 1) { CP_WAIT1(); } else { CP_WAIT0(); }
        __syncthreads();
        compute(buf, t * ROWS);
        __syncthreads();
        if (t + 2 < NTILES) {
            const int nb = (buf + 2) % 3;
            fill(nb, (t + 2) * ROWS);
            CP_COMMIT();
        }
        buf = (buf + 1) % 3;
    }
}

// ---------------------------------------------------------------------------
// Launch: memset sync (independent, first) -> single fused kernel
// ---------------------------------------------------------------------------
extern "C" void kernel_launch(void* const* d_in, const int* in_sizes, int n_in,
                              void* d_out, int out_size) {
    const float* x     = (const float*)d_in[0];
    const float* w1    = (const float*)d_in[1];
    const float* gamma = (const float*)d_in[2];
    const float* beta  = (const float*)d_in[3];
    const float* rmean = (const float*)d_in[4];
    const float* rvar  = (const float*)d_in[5];
    const float* w2    = (const float*)d_in[6];
    const float* b2    = (const float*)d_in[7];
    const float* bias  = (const float*)d_in[8];
    float* out = (float*)d_out;

    const int B = in_sizes[0] / (C_DIM * PLANE);
    const int planes = B * C_DIM;

    float* pooled;
    float* wdyn;
    int* sync;
    cudaGetSymbolAddress((void**)&pooled, g_pooled);
    cudaGetSymbolAddress((void**)&wdyn, g_wdyn);
    cudaGetSymbolAddress((void**)&sync, g_sync);

    cudaMemsetAsync(sync, 0, 2 * MAX_B * sizeof(int));
    dim3 block(32, 8);
    fused_kernel<<<planes, block>>>(x, w1, gamma, beta, rmean, rvar, w2, b2,
                                    bias, out, pooled, wdyn, sync);
}